// round 1
// baseline (speedup 1.0000x reference)
#include <cuda_runtime.h>
#include <cstdint>

#define BB 4
#define NN 65536
#define QQ 400
#define CC 20
#define MM 64
#define TPB_SORT 1024   // sort threads per batch

// ---------------- device scratch (no mallocs allowed) ----------------
__device__ float g_accX[BB*MM*QQ];     // sum x per (b,m,q)
__device__ float g_accG[BB*MM*QQ];     // sum sigmoid per (b,m,q)
__device__ float g_accL[BB*QQ];        // sum log2(1+e^{-|x|}) per (b,q)
__device__ float g_accA[BB*QQ];        // sum |x| per (b,q)
__device__ int   g_segmax[BB*MM];      // inst_seg
__device__ int   g_mstart[BB*MM];      // per-batch sorted start offset of each m
__device__ int   g_choff[BB*MM*TPB_SORT]; // per (b,m,thread) counts -> offsets
__device__ unsigned short g_sorder[BB*NN]; // point indices grouped by m

// ---------------- fast approx ops ----------------
__device__ __forceinline__ float ex2a(float x){ float r; asm("ex2.approx.f32 %0, %1;" : "=f"(r) : "f"(x)); return r; }
__device__ __forceinline__ float lg2a(float x){ float r; asm("lg2.approx.f32 %0, %1;" : "=f"(r) : "f"(x)); return r; }
__device__ __forceinline__ float rcpa(float x){ float r; asm("rcp.approx.f32 %0, %1;" : "=f"(r) : "f"(x)); return r; }

// ---------------- zero accumulators ----------------
__global__ void kzero() {
    int i = blockIdx.x * blockDim.x + threadIdx.x;  // grid covers exactly BB*MM*QQ
    g_accX[i] = 0.f;
    g_accG[i] = 0.f;
    if (i < BB*QQ) { g_accL[i] = 0.f; g_accA[i] = 0.f; }
    if (i < BB*MM) g_segmax[i] = 0;
}

// ---------------- sort pass 1: per-thread histogram + segmax ----------------
__global__ void ksort_hist(const int* __restrict__ inst, const int* __restrict__ seg) {
    int b  = blockIdx.y;
    int tt = blockIdx.x * blockDim.x + threadIdx.x;   // 0..1023
    __shared__ int smax[MM];
    if (threadIdx.x < MM) smax[threadIdx.x] = 0;
    __syncthreads();

    int cnt[MM];
    #pragma unroll
    for (int m = 0; m < MM; m++) cnt[m] = 0;

    const int* ib = inst + b * NN;
    const int* sb = seg  + b * NN;
    #pragma unroll 4
    for (int k = 0; k < NN / TPB_SORT; k++) {
        int n = tt + k * TPB_SORT;
        int m = ib[n];
        cnt[m]++;
        atomicMax(&smax[m], sb[n]);
    }
    #pragma unroll
    for (int m = 0; m < MM; m++)
        g_choff[(b * MM + m) * TPB_SORT + tt] = cnt[m];
    __syncthreads();
    if (threadIdx.x < MM)
        atomicMax(&g_segmax[b * MM + threadIdx.x], smax[threadIdx.x]);
}

// ---------------- sort pass 2: exclusive scan over [m][thread] ----------------
__global__ void ksort_scan() {
    int b = blockIdx.x;
    int t = threadIdx.x;          // 0..1023
    int* h = g_choff + b * MM * TPB_SORT;
    const int per = (MM * TPB_SORT) / 1024;   // 64 entries per thread
    int base = t * per;
    int s = 0;
    for (int k = 0; k < per; k++) s += h[base + k];

    __shared__ int sh[1024];
    sh[t] = s; __syncthreads();
    for (int d = 1; d < 1024; d <<= 1) {      // Hillis-Steele inclusive
        int v = (t >= d) ? sh[t - d] : 0;
        __syncthreads();
        sh[t] += v;
        __syncthreads();
    }
    int run = (t == 0) ? 0 : sh[t - 1];       // exclusive prefix
    for (int k = 0; k < per; k++) {
        int j = base + k;
        int c = h[j];
        h[j] = run;
        if ((j & (TPB_SORT - 1)) == 0)
            g_mstart[b * MM + (j / TPB_SORT)] = run;
        run += c;
    }
}

// ---------------- sort pass 3: deterministic scatter ----------------
__global__ void ksort_scatter(const int* __restrict__ inst) {
    int b  = blockIdx.y;
    int tt = blockIdx.x * blockDim.x + threadIdx.x;
    const int* ib = inst + b * NN;
    int* off = g_choff + b * MM * TPB_SORT;
    unsigned short* so = g_sorder + b * NN;
    #pragma unroll 4
    for (int k = 0; k < NN / TPB_SORT; k++) {
        int n = tt + k * TPB_SORT;
        int m = ib[n];
        int idx = m * TPB_SORT + tt;
        int p = off[idx];            // exclusive ownership: no atomic needed
        off[idx] = p + 1;
        so[p] = (unsigned short)n;
    }
}

// ---------------- main accumulation kernel ----------------
__global__ void __launch_bounds__(128, 7) kmain(const float* __restrict__ mask) {
    const int b    = blockIdx.z;
    const int lane = threadIdx.x & 31;
    const int w    = threadIdx.x >> 5;
    const int wc   = blockIdx.x * 4 + w;            // 0..147
    const int RPW  = (NN + 147) / 148;              // 443 rows per warp
    int i  = wc * RPW;
    const int r1 = min(i + RPW, NN);

    const int qb = blockIdx.y * 64;
    const int q0 = qb + 2 * lane;
    const bool valid = (q0 < QQ);
    const int qc = valid ? q0 : qb;                 // clamp to a sector the warp already touches

    // mstart table held across the warp's registers
    const int* ms = g_mstart + b * MM;
    const int ms0 = ms[lane];
    const int ms1 = ms[lane + 32];

    unsigned bal0 = __ballot_sync(0xffffffffu, ms0 <= i);
    unsigned bal1 = __ballot_sync(0xffffffffu, ms1 <= i);
    int m = __popc(bal0) + __popc(bal1) - 1;        // last m with start <= r0

    auto seg_end = [&](int mm) -> int {
        int nm = mm + 1;
        int lo = __shfl_sync(0xffffffffu, ms0, nm & 31);
        int hi = __shfl_sync(0xffffffffu, ms1, nm & 31);
        return (nm >= MM) ? NN : ((nm < 32) ? lo : hi);
    };

    const unsigned short* __restrict__ so = g_sorder + b * NN;
    const float* __restrict__ xb = mask + (size_t)b * NN * QQ + qc;

    float sx0 = 0.f, sx1 = 0.f, sg0 = 0.f, sg1 = 0.f;
    float L0 = 0.f, L1 = 0.f, A0 = 0.f, A1 = 0.f;
    float p0 = 1.f, p1 = 1.f;
    int cc = 0;

    const float NLOG2E = -1.4426950408889634f;

    while (i < r1) {
        while (seg_end(m) <= i) ++m;
        const int e = min(r1, seg_end(m));
        const int s0i = i;
        #pragma unroll 4
        for (; i < e; ++i) {
            int ns = so[i];                                    // uniform across warp
            float2 v = __ldg(reinterpret_cast<const float2*>(xb + (size_t)ns * QQ));
            // component 0
            {
                float x = v.x;
                float t = ex2a(fabsf(x) * NLOG2E);
                float u = 1.0f + t;
                float r = rcpa(u);
                sg0 += fabsf(r - 0.5f);
                sx0 += x;
                A0  += fabsf(x);
                p0  *= u;
            }
            // component 1
            {
                float x = v.y;
                float t = ex2a(fabsf(x) * NLOG2E);
                float u = 1.0f + t;
                float r = rcpa(u);
                sg1 += fabsf(r - 0.5f);
                sx1 += x;
                A1  += fabsf(x);
                p1  *= u;
            }
            if (((++cc) & 63) == 0) {                          // batched log flush
                L0 += lg2a(p0); p0 = 1.f;
                L1 += lg2a(p1); p1 = 1.f;
            }
        }
        // flush per-m sums (warp-uniform m)
        const int scnt = e - s0i;
        if (valid & (scnt > 0)) {
            float half = 0.5f * (float)scnt;
            float* aX = g_accX + ((b * MM + m) * QQ);
            float* aG = g_accG + ((b * MM + m) * QQ);
            atomicAdd(aX + q0,     sx0);
            atomicAdd(aX + q0 + 1, sx1);
            atomicAdd(aG + q0,     sg0 + half);
            atomicAdd(aG + q0 + 1, sg1 + half);
        }
        sx0 = sx1 = sg0 = sg1 = 0.f;
    }
    // residual product + per-q totals
    L0 += lg2a(p0);
    L1 += lg2a(p1);
    if (valid) {
        atomicAdd(g_accL + b * QQ + q0,     L0);
        atomicAdd(g_accL + b * QQ + q0 + 1, L1);
        atomicAdd(g_accA + b * QQ + q0,     A0);
        atomicAdd(g_accA + b * QQ + q0 + 1, A1);
    }
}

// ---------------- finalize: softmax + combine ----------------
__global__ void kfin(const float* __restrict__ cls, float* __restrict__ out) {
    const int q = blockIdx.x;
    const int b = blockIdx.y;
    const int m = threadIdx.x;   // 64 threads

    __shared__ float sl[CC];
    __shared__ float redG[MM];
    __shared__ float redX[MM];

    if (m < CC) sl[m] = cls[((size_t)b * QQ + q) * CC + m];

    const float X = g_accX[(b * MM + m) * QQ + q];
    const float G = g_accG[(b * MM + m) * QQ + q];
    redG[m] = G;
    redX[m] = X;
    __syncthreads();

    // redundant small softmax over C=20 (deterministic fixed order)
    float mx = -1e30f;
    #pragma unroll
    for (int c = 0; c < CC; c++) mx = fmaxf(mx, sl[c]);
    float sum = 0.f;
    #pragma unroll
    for (int c = 0; c < CC; c++) sum += __expf(sl[c] - mx);

    float sigtot = 0.f, Xtot = 0.f;
    #pragma unroll
    for (int c = 0; c < MM; c++) { sigtot += redG[c]; Xtot += redX[c]; }

    const float Atot = g_accA[b * QQ + q];
    const float Ltot = g_accL[b * QQ + q];
    const float SPtot = 0.5f * (Xtot + Atot) + 0.6931471805599453f * Ltot;

    const int st  = g_mstart[b * MM + m];
    const int en  = (m < MM - 1) ? g_mstart[b * MM + m + 1] : NN;
    const float cnt = (float)(en - st);

    const int segm = g_segmax[b * MM + m];
    const float prob = __expf(sl[segm] - mx) / sum;

    const float cmask  = (SPtot - X) * (1.0f / (float)NN);
    const float cclass = 1.0f - prob;
    const float cdice  = 1.0f - (2.0f * G + 1.0f) / (sigtot + cnt + 1.0f);

    out[((size_t)b * QQ + q) * MM + m] = cmask + cclass + cdice;
}

// ---------------- launcher ----------------
extern "C" void kernel_launch(void* const* d_in, const int* in_sizes, int n_in,
                              void* d_out, int out_size) {
    const float* mask = (const float*)d_in[0];   // [B,N,Q]
    const float* cls  = (const float*)d_in[1];   // [B,Q,C]
    const int*   inst = (const int*)d_in[2];     // [B,N]
    const int*   seg  = (const int*)d_in[3];     // [B,N]
    float*       out  = (float*)d_out;           // [B,Q,M]

    kzero<<<dim3((BB*MM*QQ)/256), 256>>>();
    ksort_hist<<<dim3(TPB_SORT/256, BB), 256>>>(inst, seg);
    ksort_scan<<<BB, 1024>>>();
    ksort_scatter<<<dim3(TPB_SORT/256, BB), 256>>>(inst);
    kmain<<<dim3(37, 7, BB), 128>>>(mask);
    kfin<<<dim3(QQ, BB), MM>>>(cls, out);
}

// round 2
// speedup vs baseline: 2.3979x; 2.3979x over previous
#include <cuda_runtime.h>
#include <cstdint>

#define BB 4
#define NN 65536
#define QQ 400
#define CC 20
#define MM 64
#define CH 2048                  // rows per sort chunk
#define NCHUNK (NN / CH)         // 32 chunks per batch

// ---------------- device scratch (no mallocs allowed) ----------------
__device__ float g_accX[BB*MM*QQ];     // sum x per (b,m,q)
__device__ float g_accG[BB*MM*QQ];     // sum (sigmoid-0.5) per (b,m,q)
__device__ float g_accL[BB*QQ];        // sum log2(1+e^{-|x|}) per (b,q)
__device__ float g_accA[BB*QQ];        // sum |x| per (b,q)
__device__ int   g_segmax[BB*MM];      // inst_seg
__device__ int   g_mstart[BB*MM];      // per-batch start offset of each m in sorted order
__device__ int   g_hist[BB*MM*NCHUNK]; // [b][m][chunk] counts -> offsets
__device__ unsigned short g_sorder[BB*NN]; // point indices grouped by m

// ---------------- fast approx ops ----------------
__device__ __forceinline__ float ex2a(float x){ float r; asm("ex2.approx.f32 %0, %1;" : "=f"(r) : "f"(x)); return r; }
__device__ __forceinline__ float lg2a(float x){ float r; asm("lg2.approx.f32 %0, %1;" : "=f"(r) : "f"(x)); return r; }
__device__ __forceinline__ float rcpa(float x){ float r; asm("rcp.approx.f32 %0, %1;" : "=f"(r) : "f"(x)); return r; }

// ---------------- zero accumulators ----------------
__global__ void kzero() {
    int i = blockIdx.x * blockDim.x + threadIdx.x;  // covers BB*MM*QQ exactly
    g_accX[i] = 0.f;
    g_accG[i] = 0.f;
    if (i < BB*QQ) { g_accL[i] = 0.f; g_accA[i] = 0.f; }
    if (i < BB*MM) g_segmax[i] = 0;
}

// ---------------- sort pass 1: per-chunk histogram + segmax ----------------
__global__ void khist(const int* __restrict__ inst, const int* __restrict__ seg) {
    const int b  = blockIdx.y;
    const int ch = blockIdx.x;
    __shared__ int h[MM];
    __shared__ int smax[MM];
    if (threadIdx.x < MM) { h[threadIdx.x] = 0; smax[threadIdx.x] = 0; }
    __syncthreads();

    const int base = b * NN + ch * CH;
    #pragma unroll
    for (int k = 0; k < CH / 256; k++) {
        int n = base + threadIdx.x + k * 256;
        int m = __ldg(inst + n);
        int s = __ldg(seg + n);
        atomicAdd(&h[m], 1);
        atomicMax(&smax[m], s);
    }
    __syncthreads();
    if (threadIdx.x < MM) {
        g_hist[(b * MM + threadIdx.x) * NCHUNK + ch] = h[threadIdx.x];
        atomicMax(&g_segmax[b * MM + threadIdx.x], smax[threadIdx.x]);
    }
}

// ---------------- sort pass 2: exclusive scan over [m][chunk] (2048/batch) ----
__global__ void kscan() {
    const int b = blockIdx.x;
    const int t = threadIdx.x;                 // 0..1023
    int* h = g_hist + b * MM * NCHUNK;         // 2048 entries
    int v0 = h[2*t], v1 = h[2*t + 1];
    __shared__ int sh[1024];
    sh[t] = v0 + v1; __syncthreads();
    for (int d = 1; d < 1024; d <<= 1) {       // Hillis-Steele inclusive
        int x = (t >= d) ? sh[t - d] : 0;
        __syncthreads();
        sh[t] += x;
        __syncthreads();
    }
    int pre = t ? sh[t - 1] : 0;               // exclusive
    h[2*t]     = pre;
    h[2*t + 1] = pre + v0;
    if (((2*t) & (NCHUNK - 1)) == 0)
        g_mstart[b * MM + (2*t) / NCHUNK] = pre;
}

// ---------------- sort pass 3: scatter via shared cursors ----------------
__global__ void kscatter(const int* __restrict__ inst) {
    const int b  = blockIdx.y;
    const int ch = blockIdx.x;
    __shared__ int cur[MM];
    if (threadIdx.x < MM)
        cur[threadIdx.x] = g_hist[(b * MM + threadIdx.x) * NCHUNK + ch];
    __syncthreads();

    const int base = ch * CH;
    unsigned short* so = g_sorder + b * NN;
    #pragma unroll
    for (int k = 0; k < CH / 256; k++) {
        int n = base + threadIdx.x + k * 256;
        int m = __ldg(inst + b * NN + n);
        int p = atomicAdd(&cur[m], 1);
        so[p] = (unsigned short)n;
    }
}

// ---------------- main accumulation kernel ----------------
#define ELEM_BODY(VX, SX, SG, AA, PP) {          \
    float x_  = (VX);                            \
    float ax_ = fabsf(x_);                       \
    float t_  = ex2a(ax_ * NLOG2E);              \
    float u_  = 1.0f + t_;                       \
    float r_  = rcpa(u_);                        \
    (SG) += copysignf(r_ - 0.5f, x_);            \
    (SX) += x_;                                  \
    (AA) += ax_;                                 \
    (PP) *= u_; }

__global__ void __launch_bounds__(128, 7) kmain(const float* __restrict__ mask) {
    const int b    = blockIdx.z;
    const int lane = threadIdx.x & 31;
    const int w    = threadIdx.x >> 5;
    const int wc   = blockIdx.x * 4 + w;            // 0..147
    const int RPW  = (NN + 147) / 148;              // 443 rows per warp
    int i  = wc * RPW;
    const int r1 = min(i + RPW, NN);

    const int qb = blockIdx.y * 64;
    const int q0 = qb + 2 * lane;
    const bool valid = (q0 < QQ);
    const int qc = valid ? q0 : qb;                 // clamp into a touched sector

    // mstart table in warp registers
    const int* ms = g_mstart + b * MM;
    const int ms0 = ms[lane];
    const int ms1 = ms[lane + 32];

    unsigned bal0 = __ballot_sync(0xffffffffu, ms0 <= i);
    unsigned bal1 = __ballot_sync(0xffffffffu, ms1 <= i);
    int m = __popc(bal0) + __popc(bal1) - 1;        // last m with start <= i

    auto seg_end = [&](int mm) -> int {
        int nm = mm + 1;
        int lo = __shfl_sync(0xffffffffu, ms0, nm & 31);
        int hi = __shfl_sync(0xffffffffu, ms1, nm & 31);
        return (nm >= MM) ? NN : ((nm < 32) ? lo : hi);
    };

    const unsigned short* __restrict__ so = g_sorder + b * NN;
    const float* __restrict__ xb = mask + (size_t)b * NN * QQ + qc;

    float L0 = 0.f, L1 = 0.f, A0 = 0.f, A1 = 0.f;
    const float NLOG2E = -1.4426950408889634f;

    while (i < r1) {
        while (seg_end(m) <= i) ++m;
        const int e   = min(r1, seg_end(m));
        const int s0i = i;
        float sx0 = 0.f, sx1 = 0.f, sg0 = 0.f, sg1 = 0.f;
        float p0 = 1.f, p1 = 1.f;

        // unroll-4 main body: batched gathers (MLP=4), unconditional log flush
        for (; i + 4 <= e; i += 4) {
            int ns0 = so[i], ns1 = so[i+1], ns2 = so[i+2], ns3 = so[i+3];
            float2 v0 = __ldg(reinterpret_cast<const float2*>(xb + (size_t)ns0 * QQ));
            float2 v1 = __ldg(reinterpret_cast<const float2*>(xb + (size_t)ns1 * QQ));
            float2 v2 = __ldg(reinterpret_cast<const float2*>(xb + (size_t)ns2 * QQ));
            float2 v3 = __ldg(reinterpret_cast<const float2*>(xb + (size_t)ns3 * QQ));
            ELEM_BODY(v0.x, sx0, sg0, A0, p0);  ELEM_BODY(v0.y, sx1, sg1, A1, p1);
            ELEM_BODY(v1.x, sx0, sg0, A0, p0);  ELEM_BODY(v1.y, sx1, sg1, A1, p1);
            ELEM_BODY(v2.x, sx0, sg0, A0, p0);  ELEM_BODY(v2.y, sx1, sg1, A1, p1);
            ELEM_BODY(v3.x, sx0, sg0, A0, p0);  ELEM_BODY(v3.y, sx1, sg1, A1, p1);
            L0 += lg2a(p0); p0 = 1.f;
            L1 += lg2a(p1); p1 = 1.f;
        }
        for (; i < e; ++i) {
            int ns = so[i];
            float2 v = __ldg(reinterpret_cast<const float2*>(xb + (size_t)ns * QQ));
            ELEM_BODY(v.x, sx0, sg0, A0, p0);
            ELEM_BODY(v.y, sx1, sg1, A1, p1);
        }
        L0 += lg2a(p0);
        L1 += lg2a(p1);

        // flush per-m sums (warp-uniform m)
        const int scnt = e - s0i;
        if (valid & (scnt > 0)) {
            float half = 0.5f * (float)scnt;
            float* aX = g_accX + ((b * MM + m) * QQ);
            float* aG = g_accG + ((b * MM + m) * QQ);
            atomicAdd(aX + q0,     sx0);
            atomicAdd(aX + q0 + 1, sx1);
            atomicAdd(aG + q0,     sg0 + half);
            atomicAdd(aG + q0 + 1, sg1 + half);
        }
    }
    if (valid) {
        atomicAdd(g_accL + b * QQ + q0,     L0);
        atomicAdd(g_accL + b * QQ + q0 + 1, L1);
        atomicAdd(g_accA + b * QQ + q0,     A0);
        atomicAdd(g_accA + b * QQ + q0 + 1, A1);
    }
}

// ---------------- finalize: softmax + combine ----------------
__global__ void kfin(const float* __restrict__ cls, float* __restrict__ out) {
    const int q = blockIdx.x;
    const int b = blockIdx.y;
    const int m = threadIdx.x;   // 64 threads

    __shared__ float sl[CC];
    __shared__ float redG[MM];
    __shared__ float redX[MM];

    if (m < CC) sl[m] = cls[((size_t)b * QQ + q) * CC + m];

    const float X = g_accX[(b * MM + m) * QQ + q];
    const float G = g_accG[(b * MM + m) * QQ + q];
    redG[m] = G;
    redX[m] = X;
    __syncthreads();

    float mx = -1e30f;
    #pragma unroll
    for (int c = 0; c < CC; c++) mx = fmaxf(mx, sl[c]);
    float sum = 0.f;
    #pragma unroll
    for (int c = 0; c < CC; c++) sum += __expf(sl[c] - mx);

    float sigtot = 0.f, Xtot = 0.f;
    #pragma unroll
    for (int c = 0; c < MM; c++) { sigtot += redG[c]; Xtot += redX[c]; }

    const float Atot = g_accA[b * QQ + q];
    const float Ltot = g_accL[b * QQ + q];
    const float SPtot = 0.5f * (Xtot + Atot) + 0.6931471805599453f * Ltot;

    const int st  = g_mstart[b * MM + m];
    const int en  = (m < MM - 1) ? g_mstart[b * MM + m + 1] : NN;
    const float cnt = (float)(en - st);

    const int segm = g_segmax[b * MM + m];
    const float prob = __expf(sl[segm] - mx) / sum;

    const float cmask  = (SPtot - X) * (1.0f / (float)NN);
    const float cclass = 1.0f - prob;
    const float cdice  = 1.0f - (2.0f * G + 1.0f) / (sigtot + cnt + 1.0f);

    out[((size_t)b * QQ + q) * MM + m] = cmask + cclass + cdice;
}

// ---------------- launcher ----------------
extern "C" void kernel_launch(void* const* d_in, const int* in_sizes, int n_in,
                              void* d_out, int out_size) {
    const float* mask = (const float*)d_in[0];   // [B,N,Q]
    const float* cls  = (const float*)d_in[1];   // [B,Q,C]
    const int*   inst = (const int*)d_in[2];     // [B,N]
    const int*   seg  = (const int*)d_in[3];     // [B,N]
    float*       out  = (float*)d_out;           // [B,Q,M]

    kzero<<<dim3((BB*MM*QQ)/256), 256>>>();
    khist<<<dim3(NCHUNK, BB), 256>>>(inst, seg);
    kscan<<<BB, 1024>>>();
    kscatter<<<dim3(NCHUNK, BB), 256>>>(inst);
    kmain<<<dim3(37, 7, BB), 128>>>(mask);
    kfin<<<dim3(QQ, BB), MM>>>(cls, out);
}

// round 3
// speedup vs baseline: 3.1832x; 1.3275x over previous
#include <cuda_runtime.h>
#include <cstdint>

#define BB 4
#define NN 65536
#define QQ 400
#define CC 20
#define MM 64
#define CH 2048                  // rows per sort chunk
#define NCHUNK (NN / CH)         // 32 chunks per batch

// ---------------- device scratch (no mallocs allowed) ----------------
__device__ float g_accX[BB*MM*QQ];     // sum x per (b,m,q)
__device__ float g_accG[BB*MM*QQ];     // sum sigmoid per (b,m,q)
__device__ float g_accL[BB*QQ];        // sum log2(prod sigma(|x|)) per (b,q)  [negative]
__device__ float g_accA[BB*QQ];        // sum |x| per (b,q)
__device__ int   g_segmax[BB*MM];      // inst_seg
__device__ int   g_mstart[BB*MM];      // per-batch start offset of each m
__device__ int   g_hist[BB*MM*NCHUNK]; // [b][m][chunk] counts -> offsets
__device__ int   g_smaxc[BB*MM*NCHUNK];// [b][m][chunk] per-chunk seg max
__device__ unsigned short g_sorder[BB*NN]; // point indices grouped by m

// ---------------- fast approx ops ----------------
__device__ __forceinline__ float tanha(float x){ float r; asm("tanh.approx.f32 %0, %1;" : "=f"(r) : "f"(x)); return r; }
__device__ __forceinline__ float lg2a(float x){ float r; asm("lg2.approx.f32 %0, %1;" : "=f"(r) : "f"(x)); return r; }

// ---------------- sort pass 1: per-chunk histogram + segmax + zero accs ------
__global__ void khist(const int* __restrict__ inst, const int* __restrict__ seg) {
    const int b  = blockIdx.y;
    const int ch = blockIdx.x;
    __shared__ int h[MM];
    __shared__ int smax[MM];
    if (threadIdx.x < MM) { h[threadIdx.x] = 0; smax[threadIdx.x] = 0; }
    __syncthreads();

    // fused zeroing of accumulators (runs before kmain, no ordering hazard)
    const int gtid = (b * NCHUNK + ch) * 256 + threadIdx.x;   // 0..32767
    #pragma unroll
    for (int j = gtid; j < BB*MM*QQ; j += BB*NCHUNK*256) {
        g_accX[j] = 0.f;
        g_accG[j] = 0.f;
    }
    if (gtid < BB*QQ) { g_accL[gtid] = 0.f; g_accA[gtid] = 0.f; }

    const int base = b * NN + ch * CH;
    #pragma unroll
    for (int k = 0; k < CH / 256; k++) {
        int n = base + threadIdx.x + k * 256;
        int m = __ldg(inst + n);
        int s = __ldg(seg + n);
        atomicAdd(&h[m], 1);
        atomicMax(&smax[m], s);
    }
    __syncthreads();
    if (threadIdx.x < MM) {
        g_hist [(b * MM + threadIdx.x) * NCHUNK + ch] = h[threadIdx.x];
        g_smaxc[(b * MM + threadIdx.x) * NCHUNK + ch] = smax[threadIdx.x];
    }
}

// ---------------- sort pass 2: exclusive scan over [m][chunk] + segmax -------
__global__ void kscan() {
    const int b = blockIdx.x;
    const int t = threadIdx.x;                 // 0..1023
    int* h = g_hist + b * MM * NCHUNK;         // 2048 entries
    int v0 = h[2*t], v1 = h[2*t + 1];
    __shared__ int sh[1024];
    sh[t] = v0 + v1; __syncthreads();
    for (int d = 1; d < 1024; d <<= 1) {       // Hillis-Steele inclusive
        int x = (t >= d) ? sh[t - d] : 0;
        __syncthreads();
        sh[t] += x;
        __syncthreads();
    }
    int pre = t ? sh[t - 1] : 0;               // exclusive
    h[2*t]     = pre;
    h[2*t + 1] = pre + v0;
    if (((2*t) & (NCHUNK - 1)) == 0)
        g_mstart[b * MM + (2*t) / NCHUNK] = pre;

    if (t < MM) {                              // reduce per-chunk segmax
        const int* sc = g_smaxc + (b * MM + t) * NCHUNK;
        int mx = 0;
        #pragma unroll
        for (int c = 0; c < NCHUNK; c++) mx = max(mx, sc[c]);
        g_segmax[b * MM + t] = mx;
    }
}

// ---------------- sort pass 3: scatter via shared cursors ----------------
__global__ void kscatter(const int* __restrict__ inst) {
    const int b  = blockIdx.y;
    const int ch = blockIdx.x;
    __shared__ int cur[MM];
    if (threadIdx.x < MM)
        cur[threadIdx.x] = g_hist[(b * MM + threadIdx.x) * NCHUNK + ch];
    __syncthreads();

    const int base = ch * CH;
    unsigned short* so = g_sorder + b * NN;
    #pragma unroll
    for (int k = 0; k < CH / 256; k++) {
        int n = base + threadIdx.x + k * 256;
        int m = __ldg(inst + b * NN + n);
        int p = atomicAdd(&cur[m], 1);
        so[p] = (unsigned short)n;
    }
}

// ---------------- main accumulation kernel ----------------
// per element: th = tanh(x/2); sigma(x)-0.5 = th/2; sigma(|x|) = 0.5+0.5|th|
// softplus log-term: log2(1+e^{-|x|}) = -log2(sigma(|x|)) -> batched product+lg2
#define ELEM_BODY(VX, SX, SG, AA, PP) {          \
    float x_  = (VX);                            \
    float th_ = tanha(0.5f * x_);                \
    (SG) += 0.5f * th_;                          \
    (SX) += x_;                                  \
    (AA) += fabsf(x_);                           \
    (PP) *= fmaf(0.5f, fabsf(th_), 0.5f); }

__global__ void __launch_bounds__(128, 7) kmain(const float* __restrict__ mask) {
    const int b    = blockIdx.z;
    const int lane = threadIdx.x & 31;
    const int w    = threadIdx.x >> 5;
    const int wc   = blockIdx.x * 4 + w;            // 0..147
    const int RPW  = (NN + 147) / 148;              // 443 rows per warp
    int i  = wc * RPW;
    const int r1 = min(i + RPW, NN);

    const int qb = blockIdx.y * 64;
    const int q0 = qb + 2 * lane;
    const bool valid = (q0 < QQ);
    const int qc = valid ? q0 : qb;                 // clamp into a touched sector

    // mstart table in warp registers
    const int* ms = g_mstart + b * MM;
    const int ms0 = ms[lane];
    const int ms1 = ms[lane + 32];

    unsigned bal0 = __ballot_sync(0xffffffffu, ms0 <= i);
    unsigned bal1 = __ballot_sync(0xffffffffu, ms1 <= i);
    int m = __popc(bal0) + __popc(bal1) - 1;        // last m with start <= i

    auto seg_end = [&](int mm) -> int {
        int nm = mm + 1;
        int lo = __shfl_sync(0xffffffffu, ms0, nm & 31);
        int hi = __shfl_sync(0xffffffffu, ms1, nm & 31);
        return (nm >= MM) ? NN : ((nm < 32) ? lo : hi);
    };

    const unsigned short* __restrict__ so = g_sorder + b * NN;
    const float* __restrict__ xb = mask + (size_t)b * NN * QQ + qc;

    float L0 = 0.f, L1 = 0.f, A0 = 0.f, A1 = 0.f;

    while (i < r1) {
        while (seg_end(m) <= i) ++m;
        const int e   = min(r1, seg_end(m));
        const int s0i = i;
        float sx0 = 0.f, sx1 = 0.f, sg0 = 0.f, sg1 = 0.f;
        float p0 = 1.f, p1 = 1.f;

        // unroll-8: front-batched index loads then 8 gathers in flight (MLP=8)
        for (; i + 8 <= e; i += 8) {
            int ns[8];
            #pragma unroll
            for (int k = 0; k < 8; k++) ns[k] = so[i + k];
            float2 v[8];
            #pragma unroll
            for (int k = 0; k < 8; k++)
                v[k] = __ldg(reinterpret_cast<const float2*>(xb + (size_t)ns[k] * QQ));
            #pragma unroll
            for (int k = 0; k < 8; k++) {
                ELEM_BODY(v[k].x, sx0, sg0, A0, p0);
                ELEM_BODY(v[k].y, sx1, sg1, A1, p1);
            }
            L0 += lg2a(p0); p0 = 1.f;               // prod of 8 sigmas in [2^-8,1]
            L1 += lg2a(p1); p1 = 1.f;
        }
        for (; i < e; ++i) {
            int ns = so[i];
            float2 v = __ldg(reinterpret_cast<const float2*>(xb + (size_t)ns * QQ));
            ELEM_BODY(v.x, sx0, sg0, A0, p0);
            ELEM_BODY(v.y, sx1, sg1, A1, p1);
        }
        L0 += lg2a(p0);
        L1 += lg2a(p1);

        // flush per-m sums (warp-uniform m, coalesced 256B atomic region)
        const int scnt = e - s0i;
        if (valid & (scnt > 0)) {
            float half = 0.5f * (float)scnt;
            float* aX = g_accX + ((b * MM + m) * QQ);
            float* aG = g_accG + ((b * MM + m) * QQ);
            atomicAdd(aX + q0,     sx0);
            atomicAdd(aX + q0 + 1, sx1);
            atomicAdd(aG + q0,     sg0 + half);
            atomicAdd(aG + q0 + 1, sg1 + half);
        }
    }
    if (valid) {
        atomicAdd(g_accL + b * QQ + q0,     L0);
        atomicAdd(g_accL + b * QQ + q0 + 1, L1);
        atomicAdd(g_accA + b * QQ + q0,     A0);
        atomicAdd(g_accA + b * QQ + q0 + 1, A1);
    }
}

// ---------------- finalize: softmax + combine ----------------
__global__ void kfin(const float* __restrict__ cls, float* __restrict__ out) {
    const int q = blockIdx.x;
    const int b = blockIdx.y;
    const int m = threadIdx.x;   // 64 threads

    __shared__ float sl[CC];
    __shared__ float redG[MM];
    __shared__ float redX[MM];

    if (m < CC) sl[m] = cls[((size_t)b * QQ + q) * CC + m];

    const float X = g_accX[(b * MM + m) * QQ + q];
    const float G = g_accG[(b * MM + m) * QQ + q];
    redG[m] = G;
    redX[m] = X;
    __syncthreads();

    float mx = -1e30f;
    #pragma unroll
    for (int c = 0; c < CC; c++) mx = fmaxf(mx, sl[c]);
    float sum = 0.f;
    #pragma unroll
    for (int c = 0; c < CC; c++) sum += __expf(sl[c] - mx);

    float sigtot = 0.f, Xtot = 0.f;
    #pragma unroll
    for (int c = 0; c < MM; c++) { sigtot += redG[c]; Xtot += redX[c]; }

    const float Atot = g_accA[b * QQ + q];
    const float Ltot = g_accL[b * QQ + q];   // = sum log2(sigma(|x|)) <= 0
    const float SPtot = 0.5f * (Xtot + Atot) - 0.6931471805599453f * Ltot;

    const int st  = g_mstart[b * MM + m];
    const int en  = (m < MM - 1) ? g_mstart[b * MM + m + 1] : NN;
    const float cnt = (float)(en - st);

    const int segm = g_segmax[b * MM + m];
    const float prob = __expf(sl[segm] - mx) / sum;

    const float cmask  = (SPtot - X) * (1.0f / (float)NN);
    const float cclass = 1.0f - prob;
    const float cdice  = 1.0f - (2.0f * G + 1.0f) / (sigtot + cnt + 1.0f);

    out[((size_t)b * QQ + q) * MM + m] = cmask + cclass + cdice;
}

// ---------------- launcher ----------------
extern "C" void kernel_launch(void* const* d_in, const int* in_sizes, int n_in,
                              void* d_out, int out_size) {
    const float* mask = (const float*)d_in[0];   // [B,N,Q]
    const float* cls  = (const float*)d_in[1];   // [B,Q,C]
    const int*   inst = (const int*)d_in[2];     // [B,N]
    const int*   seg  = (const int*)d_in[3];     // [B,N]
    float*       out  = (float*)d_out;           // [B,Q,M]

    khist<<<dim3(NCHUNK, BB), 256>>>(inst, seg);
    kscan<<<BB, 1024>>>();
    kscatter<<<dim3(NCHUNK, BB), 256>>>(inst);
    kmain<<<dim3(37, 7, BB), 128>>>(mask);
    kfin<<<dim3(QQ, BB), MM>>>(cls, out);
}